// round 1
// baseline (speedup 1.0000x reference)
#include <cuda_runtime.h>

// Problem constants
#define GN 512          // grid N
#define TB 32           // output tile (B x B)
#define TD 8            // temporal depth per launch (halo)
#define RS 48           // region size = TB + 2*TD
#define NT 384          // threads = 48 * 8
#define TOTAL_STEPS 199 // NUM_STEPS - 1 frames

// Each chunk kernel advances the state TD (or fewer) steps entirely in shared
// memory and writes each intermediate full-grid frame into d_out. The per-step
// update collapses (interior stencil + interface column + boundary copies) into:
//   new(i,j) = V(clamp(i,1,510), clamp(j,1,510))
// where V is the interface formula at column 255, else the nonlinear stencil.
// The state extends to out-of-grid coords via clamp(.,0,511), which the update
// preserves, so halo tiles at domain edges need no special casing.
__global__ __launch_bounds__(NT) void adr2m_chunk_kernel(
    const float* __restrict__ in_state,   // full 512x512 state before this chunk
    float* __restrict__ frames,           // d_out + first_frame_of_chunk * N*N
    int nsteps,                           // steps in this chunk (<= TD)
    const float* __restrict__ k1p, const float* __restrict__ k2p,
    const float* __restrict__ a1p, const float* __restrict__ a2p)
{
    __shared__ float bufA[RS][RS];
    __shared__ float bufB[RS][RS];

    const float k1 = __ldg(k1p), k2 = __ldg(k2p);
    const float a1 = __ldg(a1p), a2 = __ldg(a2p);
    const float inv_k12 = 1.0f / (k1 + k2);
    const float inv_dx2 = 511.0f * 511.0f;   // 1/dx^2, dx = 1/511
    const float inv_2dx = 511.0f * 0.5f;     // 1/(2*dx)
    const float DT = 1e-7f;

    const int r0 = (int)blockIdx.y * TB - TD;   // region origin (global coords)
    const int c0 = (int)blockIdx.x * TB - TD;
    const int tx  = (int)threadIdx.x % RS;      // region col handled by thread
    const int ty0 = (int)threadIdx.x / RS;      // 0..7, rows tx strided by 8

    // ---- load region (extended state: clamp coords to [0,511]) ----
    {
        int gj = c0 + tx;
        int lj = min(max(gj, 0), GN - 1);
        #pragma unroll
        for (int r = ty0; r < RS; r += 8) {
            int gi = r0 + r;
            int li = min(max(gi, 0), GN - 1);
            bufA[r][tx] = in_state[li * GN + lj];
        }
    }
    __syncthreads();

    float (*A)[RS]  = bufA;
    float (*Bb)[RS] = bufB;

    // per-thread column-invariant values
    const int  gj       = c0 + tx;
    const int  cj       = min(max(gj, 1), GN - 2);   // clamp(j,1,510)
    const int  pc       = cj - c0;                   // region pos of clamped col
    const bool isIface  = (cj == 255);
    const float kap     = (cj < 256) ? k1 : k2;
    const float al      = (cj < 256) ? a1 : a2;
    const bool colCentral = (tx >= TD) && (tx < TD + TB);

    for (int s = 1; s <= nsteps; ++s) {
        const int lo = s, hi = RS - 1 - s;
        float* frame = frames + (size_t)(s - 1) * GN * GN;
        #pragma unroll
        for (int r = ty0; r < RS; r += 8) {
            bool inWin = (r >= lo) && (r <= hi) && (tx >= lo) && (tx <= hi);
            if (inWin) {
                int gi = r0 + r;
                int ci = min(max(gi, 1), GN - 2);    // clamp(i,1,510)
                int pr = ci - r0;
                float Tc = A[pr][pc];
                float Tm = A[pr - 1][pc];
                float Tp = A[pr + 1][pc];
                float Tl = A[pr][pc - 1];
                float Tr = A[pr][pc + 1];
                float val;
                if (isIface) {
                    // interface column uses previous-state neighbors
                    val = (k1 * Tr + k2 * Tl) * inv_k12;
                } else {
                    float lap = (Tm + Tp + Tl + Tr - 4.0f * Tc) * inv_dx2;
                    float T_x = (Tp - Tm) * inv_2dx;
                    float T_y = (Tr - Tl) * inv_2dx;
                    float adv = (Tc * Tc * T_x - Tc * T_y) * kap;
                    float rea = kap * (Tc * Tc * Tc - Tc * Tc + Tc);
                    val = Tc + DT * (al * lap - adv + rea);
                }
                Bb[r][tx] = val;
                // write this step's frame for the tile's central B x B cells
                if (colCentral && (r >= TD) && (r < TD + TB)) {
                    frame[(size_t)(r0 + r) * GN + gj] = val;
                }
            }
        }
        __syncthreads();
        float (*tmp)[RS] = A; A = Bb; Bb = tmp;
    }
}

extern "C" void kernel_launch(void* const* d_in, const int* in_sizes, int n_in,
                              void* d_out, int out_size)
{
    (void)in_sizes; (void)n_in; (void)out_size;
    const float* u0 = (const float*)d_in[0];
    const float* k1 = (const float*)d_in[1];
    const float* k2 = (const float*)d_in[2];
    const float* a1 = (const float*)d_in[3];
    const float* a2 = (const float*)d_in[4];
    float* out = (float*)d_out;

    dim3 grid(GN / TB, GN / TB);   // 16 x 16 = 256 CTAs
    dim3 block(NT);

    int done = 0;
    const float* in_state = u0;
    while (done < TOTAL_STEPS) {
        int steps = TOTAL_STEPS - done;
        if (steps > TD) steps = TD;
        adr2m_chunk_kernel<<<grid, block>>>(
            in_state, out + (size_t)done * GN * GN, steps, k1, k2, a1, a2);
        in_state = out + (size_t)(done + steps - 1) * GN * GN;
        done += steps;
    }
}

// round 2
// speedup vs baseline: 1.3136x; 1.3136x over previous
#include <cuda_runtime.h>

#define GN 512          // grid N
#define TB 32           // central output tile
#define TD 8            // temporal depth per launch
#define RS 48           // region = TB + 2*TD
#define RSP 50          // padded region dim (1-cell garbage ring)
#define NT 384          // 48 cols x 8 row-strips
#define TOTAL_STEPS 199

// Per-step rule (interior stencil + interface col 255 + boundary copies) collapses to
//   new(i,j) = V(clamp(i,1,510), clamp(j,1,510)),  state extended by clamp(.,0,511).
// Strategy: compute the FULL 48x48 region every step (no shrinking window).
// The pad ring holds garbage; wrong values propagate inward 1 cell/step, so the
// central 32x32 (depth >= TD) is exact for all TD steps. Column clamps are folded
// into a per-thread hoisted smem column (pcp); row clamps are realized as a single
// duplicate store on the by==0 / by==15 tiles (row 0 := row 1, row 511 := row 510),
// issued after the nominal store in the same thread so program order wins.
__global__ __launch_bounds__(NT) void adr_chunk(
    const float* __restrict__ in_state,
    float* __restrict__ frames,           // frame for step 1 of this chunk
    int nsteps,
    const float* __restrict__ k1p, const float* __restrict__ k2p,
    const float* __restrict__ a1p, const float* __restrict__ a2p)
{
    __shared__ float buf[2][RSP][RSP];

    const float k1 = __ldg(k1p), k2 = __ldg(k2p);
    const float a1 = __ldg(a1p), a2 = __ldg(a2p);
    const float inv_k12 = 1.0f / (k1 + k2);
    const float inv_dx2 = 511.0f * 511.0f;   // 1/dx^2, dx = 1/511
    const float inv_2dx = 255.5f;            // 1/(2 dx)
    const float DTC = 1e-7f;

    const int by = blockIdx.y;
    const int r0 = by * TB - TD;
    const int c0 = (int)blockIdx.x * TB - TD;
    const int tx = (int)threadIdx.x % RS;    // region column 0..47
    const int ty = (int)threadIdx.x / RS;    // 0..7, contiguous 6-row strip
    const int rbase = ty * 6;

    // column-invariant, hoisted per thread
    const int  gj  = c0 + tx;
    const int  cj  = min(max(gj, 1), GN - 2);
    const int  pcp = cj - c0 + 1;            // padded smem col of clamped j
    const bool isIface = (cj == 255);
    const float kap = (cj < 256) ? k1 : k2;
    const float al  = (cj < 256) ? a1 : a2;
    const bool colC = (tx >= TD) && (tx < TD + TB);
    const bool fix0  = (by == 0)           && (ty == 1); // strip owning region row 9 (global row 1)
    const bool fix15 = (by == GN/TB - 1)   && (ty == 6); // strip owning region rows 38/39

    // ---- load 48x48 region (extended state via clamp); pad ring stays garbage ----
    {
        const int lj = min(max(gj, 0), GN - 1);
        #pragma unroll
        for (int rr = 0; rr < 6; ++rr) {
            int gi = r0 + rbase + rr;
            int li = min(max(gi, 0), GN - 1);
            buf[0][rbase + rr + 1][tx + 1] = in_state[li * GN + lj];
        }
    }
    __syncthreads();

    int cur = 0;
    float* frame = frames;
    #pragma unroll 1
    for (int s = 0; s < nsteps; ++s) {
        const float (*A)[RSP] = buf[cur];
        float (*B)[RSP] = buf[cur ^ 1];

        float Tm = A[rbase][pcp];
        float Tc = A[rbase + 1][pcp];
        float fixval = 0.0f;

        #pragma unroll
        for (int rr = 0; rr < 6; ++rr) {
            const int r = rbase + rr;
            float Tp = A[r + 2][pcp];
            float Tl = A[r + 1][pcp - 1];
            float Tr = A[r + 1][pcp + 1];
            float val;
            if (isIface) {
                val = (k1 * Tr + k2 * Tl) * inv_k12;  // reads previous state
            } else {
                float lap = (Tm + Tp + Tl + Tr - 4.0f * Tc) * inv_dx2;
                float T_x = (Tp - Tm) * inv_2dx;
                float T_y = (Tr - Tl) * inv_2dx;
                float adv = (Tc * Tc * T_x - Tc * T_y) * kap;
                float rea = kap * (Tc * Tc * Tc - Tc * Tc + Tc);
                val = Tc + DTC * (al * lap - adv + rea);
            }
            B[r + 1][tx + 1] = val;

            bool rowC = (r >= TD) && (r < TD + TB);
            if (colC && rowC) frame[(size_t)(r0 + r) * GN + gj] = val;

            if (rr == 2) fixval = val;           // region row 38 value (used by fix15)
            if (rr == 3) {
                if (fix0) {                      // region row 9 (global 1) -> also row 8 (global 0)
                    B[9][tx + 1] = val;
                    if (colC) frame[gj] = val;
                }
                if (fix15) {                     // region row 39 (global 511) := row 38 (global 510)
                    B[40][tx + 1] = fixval;
                    if (colC) frame[(size_t)(GN - 1) * GN + gj] = fixval;
                }
            }
            Tm = Tc; Tc = Tp;
        }
        __syncthreads();
        cur ^= 1;
        frame += (size_t)GN * GN;
    }
}

extern "C" void kernel_launch(void* const* d_in, const int* in_sizes, int n_in,
                              void* d_out, int out_size)
{
    (void)in_sizes; (void)n_in; (void)out_size;
    const float* u0 = (const float*)d_in[0];
    const float* k1 = (const float*)d_in[1];
    const float* k2 = (const float*)d_in[2];
    const float* a1 = (const float*)d_in[3];
    const float* a2 = (const float*)d_in[4];
    float* out = (float*)d_out;

    dim3 grid(GN / TB, GN / TB);   // 16x16 = 256 CTAs
    dim3 block(NT);

    int done = 0;
    const float* src = u0;
    while (done < TOTAL_STEPS) {
        int steps = TOTAL_STEPS - done;
        if (steps > TD) steps = TD;
        adr_chunk<<<grid, block>>>(src, out + (size_t)done * GN * GN, steps,
                                   k1, k2, a1, a2);
        src = out + (size_t)(done + steps - 1) * GN * GN;
        done += steps;
    }
}

// round 3
// speedup vs baseline: 1.4417x; 1.0976x over previous
#include <cuda_runtime.h>

#define GN 512
#define TB 32           // central output tile
#define TD 8            // temporal depth per launch
#define RS 48           // region = TB + 2*TD
#define ROWS_P 50       // padded smem rows (1 garbage ring)
#define COLS_P 52       // padded smem row stride in floats (pairs 8B-aligned)
#define NPAIR 24        // column pairs per region
#define NT 384          // 24 pairs x 16 strips (3 rows each)
#define TOTAL_STEPS 199

typedef unsigned long long u64;

__device__ __forceinline__ u64 PK(float a, float b) {
    u64 r; asm("mov.b64 %0,{%1,%2};" : "=l"(r) : "f"(a), "f"(b)); return r;
}
__device__ __forceinline__ void UNPK(u64 v, float& a, float& b) {
    asm("mov.b64 {%0,%1},%2;" : "=f"(a), "=f"(b) : "l"(v));
}
__device__ __forceinline__ u64 ADD2(u64 a, u64 b) {
    u64 d; asm("add.rn.f32x2 %0,%1,%2;" : "=l"(d) : "l"(a), "l"(b)); return d;
}
__device__ __forceinline__ u64 MUL2(u64 a, u64 b) {
    u64 d; asm("mul.rn.f32x2 %0,%1,%2;" : "=l"(d) : "l"(a), "l"(b)); return d;
}
__device__ __forceinline__ u64 FMA2(u64 a, u64 b, u64 c) {
    u64 d; asm("fma.rn.f32x2 %0,%1,%2,%3;" : "=l"(d) : "l"(a), "l"(b), "l"(c)); return d;
}

// Per-step rule collapses to new(i,j) = V(clamp(i,1,510), clamp(j,1,510)), with the
// state extended by clamp(.,0,511). Full 48x48 region recomputed every step inside a
// garbage-padded 50x52 smem buffer; contamination moves 1 cell/step so the central
// 32x32 (depth >= TD) stays exact for TD steps. Each thread owns a column PAIR and a
// 3-row strip; all stencil math is packed f32x2. Specials:
//   pair (254,255): single material (k1); iface override on .y lane only.
//   col 0 / col 511 copies: in-register lane swap (val.x=val.y / val.y=val.x).
//   row 0 / row 511 copies: suppress the garbage nominal store, duplicate-store from
//   the thread that owns the source row (no smem race).
__global__ __launch_bounds__(NT) void adr_chunk(
    const float* __restrict__ in_state,
    float* __restrict__ frames,
    int nsteps,
    const float* __restrict__ k1p, const float* __restrict__ k2p,
    const float* __restrict__ a1p, const float* __restrict__ a2p)
{
    __shared__ __align__(16) float buf[2][ROWS_P][COLS_P];

    const float k1 = __ldg(k1p), k2 = __ldg(k2p);
    const float a1 = __ldg(a1p), a2 = __ldg(a2p);
    const float inv_k12 = 1.0f / (k1 + k2);
    const float inv_dx2 = 511.0f * 511.0f;
    const float inv_2dx = 255.5f;
    const float DTC = 1e-7f;

    const int by = blockIdx.y, bx = blockIdx.x;
    const int r0 = by * TB - TD;
    const int c0 = bx * TB - TD;
    const int tx = (int)threadIdx.x % NPAIR;   // pair index 0..23
    const int ty = (int)threadIdx.x / NPAIR;   // strip 0..15
    const int rbase = ty * 3;
    const int gj0 = c0 + 2 * tx;               // even global col of pair
    const int sc  = 2 * tx + 2;                // smem col of pair lo (8B aligned)

    // pair-uniform material (boundary at 256 is pair-aligned)
    const float kap = (gj0 < 256) ? k1 : k2;
    const float al  = (gj0 < 256) ? a1 : a2;

    const float A1 = DTC * al * inv_dx2;
    const u64 cA1   = PK(A1, A1);
    const u64 cM4A1 = PK(-4.0f * A1, -4.0f * A1);
    const u64 cM1   = PK(-1.0f, -1.0f);
    const u64 cONE  = PK(1.0f, 1.0f);
    const u64 cI2   = PK(inv_2dx, inv_2dx);
    const u64 cMI2  = PK(-inv_2dx, -inv_2dx);
    const u64 cB1   = PK(DTC * kap, DTC * kap);

    const bool colC = (tx >= 4) && (tx <= 19);           // pair in central cols
    const bool isI  = (gj0 == 254);
    const bool isL  = (gj0 == 0);
    const bool isR  = (gj0 == 510);
    const bool supTop = (by == 0)  && (ty == 2);   // rr==2 nominal store of global row 0
    const bool fixTop = (by == 0)  && (ty == 3);   // rr==0 owns global row 1
    const bool supBot = (by == GN/TB - 1) && (ty == 13); // rr==0 nominal store of row 511
    const bool fixBot = (by == GN/TB - 1) && (ty == 12); // rr==2 owns global row 510
    const bool rowC0 = (rbase     >= 8) && (rbase     <= 39);
    const bool rowC1 = (rbase + 1 >= 8) && (rbase + 1 <= 39);
    const bool rowC2 = (rbase + 2 >= 8) && (rbase + 2 <= 39);

    // ---- load region (extended state via clamp); pad ring stays garbage ----
    {
        const bool canVec = (gj0 >= 0) && (gj0 <= 510);
        const int lj0 = min(max(gj0, 0), GN - 1);
        const int lj1 = min(max(gj0 + 1, 0), GN - 1);
        #pragma unroll
        for (int rr = 0; rr < 3; ++rr) {
            int gi = r0 + rbase + rr;
            int li = min(max(gi, 0), GN - 1);
            float x, y;
            if (canVec) {
                float2 v = *(const float2*)&in_state[(size_t)li * GN + gj0];
                x = v.x; y = v.y;
            } else {
                x = in_state[(size_t)li * GN + lj0];
                y = in_state[(size_t)li * GN + lj1];
            }
            *(float2*)&buf[0][rbase + rr + 1][sc] = make_float2(x, y);
        }
    }
    __syncthreads();

    int cur = 0;
    float* frame = frames;
    #pragma unroll 1
    for (int s = 0; s < nsteps; ++s) {
        const float (*A)[COLS_P] = buf[cur];
        float (*B)[COLS_P] = buf[cur ^ 1];

        u64 Tm = *(const u64*)&A[rbase][sc];
        u64 Tc = *(const u64*)&A[rbase + 1][sc];

        #pragma unroll
        for (int rr = 0; rr < 3; ++rr) {
            const int r = rbase + rr;
            u64 Tp = *(const u64*)&A[r + 2][sc];
            float TlS = A[r + 1][sc - 1];
            float TrS = A[r + 1][sc + 2];
            float cx, cy; UNPK(Tc, cx, cy);
            u64 L = PK(TlS, cx);
            u64 R = PK(cy, TrS);

            u64 sum  = ADD2(ADD2(Tm, Tp), ADD2(L, R));
            u64 lapc = FMA2(Tc, cM4A1, MUL2(sum, cA1));   // DT*al*lap
            u64 dxv  = FMA2(Tm, cM1, Tp);                  // Tp - Tm
            u64 dyv  = FMA2(L,  cM1, R);                   // R - L
            u64 P    = FMA2(dxv, cMI2, ADD2(Tc, cM1));     // (c-1) - T_x
            u64 Q    = FMA2(dyv, cI2,  cONE);              // T_y + 1
            u64 c2   = MUL2(Tc, Tc);
            u64 cQ   = MUL2(Tc, Q);
            u64 S    = FMA2(c2, P, cQ);                    // c^2*P + c*Q
            u64 val  = ADD2(Tc, FMA2(S, cB1, lapc));

            if (isI) {        // col 255: interface (reads prev state)
                float vx, vy; UNPK(val, vx, vy);
                vy = fmaf(k1, TrS, k2 * cx) * inv_k12;
                val = PK(vx, vy);
            } else if (isL) { // col 0 := col 1
                float vx, vy; UNPK(val, vx, vy);
                val = PK(vy, vy);
            } else if (isR) { // col 511 := col 510
                float vx, vy; UNPK(val, vx, vy);
                val = PK(vx, vx);
            }

            const bool sup = (rr == 2 && supTop) || (rr == 0 && supBot);
            if (!sup) *(u64*)&B[r + 1][sc] = val;
            const bool rowC = (rr == 0) ? rowC0 : (rr == 1) ? rowC1 : rowC2;
            if (colC && rowC && !sup)
                *(u64*)&frame[(size_t)(r0 + r) * GN + gj0] = val;

            if (rr == 0 && fixTop) {       // global row 0 := row 1
                *(u64*)&B[9][sc] = val;
                if (colC) *(u64*)&frame[gj0] = val;
            }
            if (rr == 2 && fixBot) {       // global row 511 := row 510
                *(u64*)&B[40][sc] = val;
                if (colC) *(u64*)&frame[(size_t)(GN - 1) * GN + gj0] = val;
            }

            Tm = Tc; Tc = Tp;
        }
        __syncthreads();
        cur ^= 1;
        frame += (size_t)GN * GN;
    }
}

extern "C" void kernel_launch(void* const* d_in, const int* in_sizes, int n_in,
                              void* d_out, int out_size)
{
    (void)in_sizes; (void)n_in; (void)out_size;
    const float* u0 = (const float*)d_in[0];
    const float* k1 = (const float*)d_in[1];
    const float* k2 = (const float*)d_in[2];
    const float* a1 = (const float*)d_in[3];
    const float* a2 = (const float*)d_in[4];
    float* out = (float*)d_out;

    dim3 grid(GN / TB, GN / TB);   // 16x16 = 256 CTAs
    dim3 block(NT);

    int done = 0;
    const float* src = u0;
    while (done < TOTAL_STEPS) {
        int steps = TOTAL_STEPS - done;
        if (steps > TD) steps = TD;
        adr_chunk<<<grid, block>>>(src, out + (size_t)done * GN * GN, steps,
                                   k1, k2, a1, a2);
        src = out + (size_t)(done + steps - 1) * GN * GN;
        done += steps;
    }
}

// round 4
// speedup vs baseline: 1.6196x; 1.1233x over previous
#include <cuda_runtime.h>

#define GN 512
#define TBR 64          // tile rows
#define TBC 32          // tile cols
#define TD 8            // temporal depth per launch
#define ROWS_P 82       // padded smem rows: 80 region + garbage ring
#define COLS_P 52       // padded smem row stride (floats)
#define NPAIR 24        // column pairs per region (48 cols)
#define NT 960          // 24 pairs x 40 two-row strips
#define TOTAL_STEPS 199

typedef unsigned long long u64;

__device__ __forceinline__ u64 PK(float a, float b) {
    u64 r; asm("mov.b64 %0,{%1,%2};" : "=l"(r) : "f"(a), "f"(b)); return r;
}
__device__ __forceinline__ void UNPK(u64 v, float& a, float& b) {
    asm("mov.b64 {%0,%1},%2;" : "=f"(a), "=f"(b) : "l"(v));
}
__device__ __forceinline__ u64 ADD2(u64 a, u64 b) {
    u64 d; asm("add.rn.f32x2 %0,%1,%2;" : "=l"(d) : "l"(a), "l"(b)); return d;
}
__device__ __forceinline__ u64 MUL2(u64 a, u64 b) {
    u64 d; asm("mul.rn.f32x2 %0,%1,%2;" : "=l"(d) : "l"(a), "l"(b)); return d;
}
__device__ __forceinline__ u64 FMA2(u64 a, u64 b, u64 c) {
    u64 d; asm("fma.rn.f32x2 %0,%1,%2,%3;" : "=l"(d) : "l"(a), "l"(b), "l"(c)); return d;
}

// new(i,j) = V(clamp(i,1,510), clamp(j,1,510)); state extended by clamp(.,0,511).
// 64x32 tiles -> 128 CTAs = one per SM (single balanced wave on 148 SMs).
// Full 80x48 region recomputed per step in a garbage-padded 82x52 smem buffer;
// contamination moves 1 cell/step, central 64x32 (depth >= 9 from the ring) is
// exact for TD=8 steps. Thread = column pair x 2-row strip; packed f32x2 math.
// Specials: pair(254,255) single material + iface .y override; col 0/511 copies
// are lane swaps; row 0/511 copies are same-thread suppress+duplicate stores
// (ty==4 owns global rows 0,1; ty==35 owns 510,511).
__global__ __launch_bounds__(NT) void adr_chunk(
    const float* __restrict__ in_state,
    float* __restrict__ frames,
    int nsteps,
    const float* __restrict__ k1p, const float* __restrict__ k2p,
    const float* __restrict__ a1p, const float* __restrict__ a2p)
{
    __shared__ __align__(16) float buf[2][ROWS_P][COLS_P];

    const float k1 = __ldg(k1p), k2 = __ldg(k2p);
    const float a1 = __ldg(a1p), a2 = __ldg(a2p);
    const float inv_k12 = 1.0f / (k1 + k2);
    const float inv_dx2 = 511.0f * 511.0f;
    const float inv_2dx = 255.5f;
    const float DTC = 1e-7f;

    const int by = blockIdx.y, bx = blockIdx.x;
    const int r0 = by * TBR - TD;
    const int c0 = bx * TBC - TD;
    const int tx = (int)threadIdx.x % NPAIR;   // pair 0..23
    const int ty = (int)threadIdx.x / NPAIR;   // strip 0..39 (2 rows each)
    const int rbase = ty * 2;                  // region row of strip start
    const int gj0 = c0 + 2 * tx;               // even global col of pair
    const int sc  = 2 * tx + 2;                // smem col of pair lo (8B aligned)

    const float kap = (gj0 < 256) ? k1 : k2;   // material boundary pair-aligned
    const float al  = (gj0 < 256) ? a1 : a2;

    const float A1 = DTC * al * inv_dx2;
    const u64 cA1   = PK(A1, A1);
    const u64 cM4A1 = PK(-4.0f * A1, -4.0f * A1);
    const u64 cM1   = PK(-1.0f, -1.0f);
    const u64 cONE  = PK(1.0f, 1.0f);
    const u64 cI2   = PK(inv_2dx, inv_2dx);
    const u64 cMI2  = PK(-inv_2dx, -inv_2dx);
    const u64 cB1   = PK(DTC * kap, DTC * kap);

    const bool colC = (tx >= 4) && (tx <= 19);         // central 32 cols
    const bool rowC = (ty >= 4) && (ty <= 35);         // central 64 rows
    const bool isI  = (gj0 == 254);
    const bool isL  = (gj0 == 0);
    const bool isR  = (gj0 == 510);
    const bool topFix = (by == 0) && (ty == 4);        // owns global rows 0,1
    const bool botFix = (by == GN/TBR - 1) && (ty == 35); // owns 510,511

    // ---- load region (extended via clamp); pad ring stays garbage ----
    {
        const bool canVec = (gj0 >= 0) && (gj0 <= 510);
        const int lj0 = min(max(gj0, 0), GN - 1);
        const int lj1 = min(max(gj0 + 1, 0), GN - 1);
        #pragma unroll
        for (int rr = 0; rr < 2; ++rr) {
            int gi = r0 + rbase + rr;
            int li = min(max(gi, 0), GN - 1);
            float x, y;
            if (canVec) {
                float2 v = *(const float2*)&in_state[(size_t)li * GN + gj0];
                x = v.x; y = v.y;
            } else {
                x = in_state[(size_t)li * GN + lj0];
                y = in_state[(size_t)li * GN + lj1];
            }
            *(float2*)&buf[0][rbase + rr + 1][sc] = make_float2(x, y);
        }
    }
    __syncthreads();

    int cur = 0;
    float* frame = frames;
    #pragma unroll 1
    for (int s = 0; s < nsteps; ++s) {
        const float (*A)[COLS_P] = buf[cur];
        float (*B)[COLS_P] = buf[cur ^ 1];

        u64 Tm = *(const u64*)&A[rbase][sc];
        u64 Tc = *(const u64*)&A[rbase + 1][sc];
        u64 keep = 0;   // botFix: value of global row 510

        #pragma unroll
        for (int rr = 0; rr < 2; ++rr) {
            const int r = rbase + rr;              // region row
            u64 Tp = *(const u64*)&A[r + 2][sc];
            float TlS = A[r + 1][sc - 1];
            float TrS = A[r + 1][sc + 2];
            float cx, cy; UNPK(Tc, cx, cy);
            u64 L = PK(TlS, cx);
            u64 R = PK(cy, TrS);

            u64 sum  = ADD2(ADD2(Tm, Tp), ADD2(L, R));
            u64 lapc = FMA2(Tc, cM4A1, MUL2(sum, cA1));   // DT*al*lap
            u64 dxv  = FMA2(Tm, cM1, Tp);                  // Tp - Tm
            u64 dyv  = FMA2(L,  cM1, R);                   // R - L
            u64 P    = FMA2(dxv, cMI2, ADD2(Tc, cM1));     // (c-1) - T_x
            u64 Q    = FMA2(dyv, cI2,  cONE);              // T_y + 1
            u64 c2   = MUL2(Tc, Tc);
            u64 cQ   = MUL2(Tc, Q);
            u64 S    = FMA2(c2, P, cQ);                    // c^2*P + c*Q
            u64 val  = ADD2(Tc, FMA2(S, cB1, lapc));

            if (isI) {        // col 255 interface (reads prev state)
                float vx, vy; UNPK(val, vx, vy);
                vy = fmaf(k1, TrS, k2 * cx) * inv_k12;
                val = PK(vx, vy);
            } else if (isL) { // col 0 := col 1
                float vx, vy; UNPK(val, vx, vy);
                val = PK(vy, vy);
            } else if (isR) { // col 511 := col 510
                float vx, vy; UNPK(val, vx, vy);
                val = PK(vx, vx);
            }

            // suppress garbage stores of boundary rows (overwritten by dups)
            const bool sup = (rr == 0 && topFix) || (rr == 1 && botFix);
            if (!sup) {
                *(u64*)&B[r + 1][sc] = val;
                if (colC && rowC)
                    *(u64*)&frame[(size_t)(r0 + r) * GN + gj0] = val;
            }
            if (rr == 0 && botFix) keep = val;    // global row 510
            if (rr == 1 && topFix) {              // row 0 := row 1 (region 8 := 9)
                *(u64*)&B[9][sc] = val;
                if (colC) *(u64*)&frame[gj0] = val;
            }
            if (rr == 1 && botFix) {              // row 511 := row 510
                *(u64*)&B[72][sc] = keep;
                if (colC) *(u64*)&frame[(size_t)(GN - 1) * GN + gj0] = keep;
            }

            Tm = Tc; Tc = Tp;
        }
        __syncthreads();
        cur ^= 1;
        frame += (size_t)GN * GN;
    }
}

extern "C" void kernel_launch(void* const* d_in, const int* in_sizes, int n_in,
                              void* d_out, int out_size)
{
    (void)in_sizes; (void)n_in; (void)out_size;
    const float* u0 = (const float*)d_in[0];
    const float* k1 = (const float*)d_in[1];
    const float* k2 = (const float*)d_in[2];
    const float* a1 = (const float*)d_in[3];
    const float* a2 = (const float*)d_in[4];
    float* out = (float*)d_out;

    dim3 grid(GN / TBC, GN / TBR);   // 16 x 8 = 128 CTAs (one per SM)
    dim3 block(NT);

    int done = 0;
    const float* src = u0;
    while (done < TOTAL_STEPS) {
        int steps = TOTAL_STEPS - done;
        if (steps > TD) steps = TD;
        adr_chunk<<<grid, block>>>(src, out + (size_t)done * GN * GN, steps,
                                   k1, k2, a1, a2);
        src = out + (size_t)(done + steps - 1) * GN * GN;
        done += steps;
    }
}

// round 5
// speedup vs baseline: 1.8408x; 1.1366x over previous
#include <cuda_runtime.h>

#define GN 512
#define TBR 64          // tile rows
#define TBC 32          // tile cols
#define TD 8            // max temporal depth per launch
#define ROWS_P 82       // padded smem rows (region 80 + ring)
#define COLS_P 52       // padded smem row stride (floats)
#define NPAIR 24        // column pairs per region (48 cols)
#define NT 960          // 24 pairs x 40 two-row strips
#define TOTAL_STEPS 199

typedef unsigned long long u64;

__device__ __forceinline__ u64 PK(float a, float b) {
    u64 r; asm("mov.b64 %0,{%1,%2};" : "=l"(r) : "f"(a), "f"(b)); return r;
}
__device__ __forceinline__ void UNPK(u64 v, float& a, float& b) {
    asm("mov.b64 {%0,%1},%2;" : "=f"(a), "=f"(b) : "l"(v));
}
__device__ __forceinline__ u64 ADD2(u64 a, u64 b) {
    u64 d; asm("add.rn.f32x2 %0,%1,%2;" : "=l"(d) : "l"(a), "l"(b)); return d;
}
__device__ __forceinline__ u64 MUL2(u64 a, u64 b) {
    u64 d; asm("mul.rn.f32x2 %0,%1,%2;" : "=l"(d) : "l"(a), "l"(b)); return d;
}
__device__ __forceinline__ u64 FMA2(u64 a, u64 b, u64 c) {
    u64 d; asm("fma.rn.f32x2 %0,%1,%2,%3;" : "=l"(d) : "l"(a), "l"(b), "l"(c)); return d;
}

// new(i,j) = V(clamp(i,1,510), clamp(j,1,510)); state extended by clamp(.,0,511).
// 64x32 tiles -> 128 CTAs, one per SM. Full 80x48 region recomputed per step in a
// garbage-ringed 82x52 smem buffer; contamination creeps 1 cell/step so the central
// 64x32 stays exact for up to 8 steps. NSTEPS templated -> fully unrolled step loop:
// static ping-pong, immediate-offset smem & frame addressing. Specials (interface
// col 255, copy cols 0/511) are branchless SELP blends; copy rows 0/511 are
// same-thread overwrite fixups (program order wins, no suppression needed).
template <int NSTEPS>
__global__ __launch_bounds__(NT) void adr_chunk(
    const float* __restrict__ in_state,
    float* __restrict__ frames,
    const float* __restrict__ k1p, const float* __restrict__ k2p,
    const float* __restrict__ a1p, const float* __restrict__ a2p)
{
    __shared__ __align__(16) float buf[2][ROWS_P][COLS_P];

    const float k1 = __ldg(k1p), k2 = __ldg(k2p);
    const float a1 = __ldg(a1p), a2 = __ldg(a2p);
    const float inv_k12 = 1.0f / (k1 + k2);
    const float inv_dx2 = 511.0f * 511.0f;
    const float inv_2dx = 255.5f;
    const float DTC = 1e-7f;

    const int by = blockIdx.y, bx = blockIdx.x;
    const int r0 = by * TBR - TD;
    const int c0 = bx * TBC - TD;
    const int tx = (int)threadIdx.x % NPAIR;   // pair 0..23
    const int ty = (int)threadIdx.x / NPAIR;   // strip 0..39 (2 rows)
    const int rbase = ty * 2;                  // region row of strip start
    const int gj0 = c0 + 2 * tx;
    const int sc  = 2 * tx + 2;                // smem col of pair lo (8B aligned)

    const float kap = (gj0 < 256) ? k1 : k2;
    const float al  = (gj0 < 256) ? a1 : a2;

    const float A1 = DTC * al * inv_dx2;
    const u64 cA1   = PK(A1, A1);
    const u64 cM4A1 = PK(-4.0f * A1, -4.0f * A1);
    const u64 cM1   = PK(-1.0f, -1.0f);
    const u64 cONE  = PK(1.0f, 1.0f);
    const u64 cI2   = PK(inv_2dx, inv_2dx);
    const u64 cMI2  = PK(-inv_2dx, -inv_2dx);
    const u64 cB1   = PK(DTC * kap, DTC * kap);

    const bool colC = (tx >= 4) && (tx <= 19);
    const bool rowC = (ty >= 4) && (ty <= 35);
    const bool storeC = colC && rowC;
    const bool isI  = (gj0 == 254);
    const bool isL  = (gj0 == 0);
    const bool isR  = (gj0 == 510);
    const bool topFix = (by == 0) && (ty == 4);            // global rows 0,1
    const bool botFix = (by == GN / TBR - 1) && (ty == 35); // global rows 510,511

    // one stencil-point pair, branchless specials
    auto point = [&](u64 Tm, u64 Tc, u64 Tp, float TlS, float TrS) -> u64 {
        float cx, cy; UNPK(Tc, cx, cy);
        u64 L = PK(TlS, cx);
        u64 R = PK(cy, TrS);
        u64 sum  = ADD2(ADD2(Tm, Tp), ADD2(L, R));
        u64 lapc = FMA2(Tc, cM4A1, MUL2(sum, cA1));   // DT*al*lap
        u64 dxv  = FMA2(Tm, cM1, Tp);                  // Tp - Tm
        u64 dyv  = FMA2(L,  cM1, R);                   // R - L
        u64 P    = FMA2(dxv, cMI2, ADD2(Tc, cM1));     // (c-1) - T_x
        u64 Q    = FMA2(dyv, cI2,  cONE);              // T_y + 1
        u64 S    = FMA2(MUL2(Tc, Tc), P, MUL2(Tc, Q)); // c^2*P + c*Q
        u64 val  = ADD2(Tc, FMA2(S, cB1, lapc));
        float vx, vy; UNPK(val, vx, vy);
        float ifv = fmaf(k1, TrS, k2 * cx) * inv_k12;  // interface (prev state)
        float ry = isI ? ifv : vy;
        float rx = isL ? ry  : vx;                     // col 0 := col 1
        float fy = isR ? vx  : ry;                     // col 511 := col 510
        return PK(rx, fy);
    };

    // ---- load region (extended via clamp); pad ring stays garbage ----
    {
        const bool canVec = (gj0 >= 0) && (gj0 <= 510);
        const int lj0 = min(max(gj0, 0), GN - 1);
        const int lj1 = min(max(gj0 + 1, 0), GN - 1);
        #pragma unroll
        for (int rr = 0; rr < 2; ++rr) {
            int gi = r0 + rbase + rr;
            int li = min(max(gi, 0), GN - 1);
            float x, y;
            if (canVec) {
                float2 v = *(const float2*)&in_state[(size_t)li * GN + gj0];
                x = v.x; y = v.y;
            } else {
                x = in_state[(size_t)li * GN + lj0];
                y = in_state[(size_t)li * GN + lj1];
            }
            *(float2*)&buf[0][rbase + rr + 1][sc] = make_float2(x, y);
        }
    }
    __syncthreads();

    float* const fr0 = frames + (ptrdiff_t)(r0 + rbase) * GN + gj0;

    #pragma unroll
    for (int s = 0; s < NSTEPS; ++s) {
        const float (*A)[COLS_P] = buf[s & 1];
        float (*B)[COLS_P] = buf[(s & 1) ^ 1];
        float* f0 = fr0 + (size_t)s * (GN * GN);

        u64 V0 = *(const u64*)&A[rbase + 0][sc];
        u64 V1 = *(const u64*)&A[rbase + 1][sc];
        u64 V2 = *(const u64*)&A[rbase + 2][sc];
        u64 V3 = *(const u64*)&A[rbase + 3][sc];

        u64 keep;
        {   // row 0 of strip (region row rbase)
            float TlS = A[rbase + 1][sc - 1];
            float TrS = A[rbase + 1][sc + 2];
            u64 val = point(V0, V1, V2, TlS, TrS);
            *(u64*)&B[rbase + 1][sc] = val;
            if (storeC) *(u64*)&f0[0] = val;
            keep = val;                          // botFix: global row 510
        }
        {   // row 1 of strip (region row rbase+1)
            float TlS = A[rbase + 2][sc - 1];
            float TrS = A[rbase + 2][sc + 2];
            u64 val = point(V1, V2, V3, TlS, TrS);
            *(u64*)&B[rbase + 2][sc] = val;
            if (storeC) *(u64*)&f0[GN] = val;
            if (topFix) {                        // row 0 := row 1 (same thread overwrites)
                *(u64*)&B[9][sc] = val;
                if (colC) *(u64*)&f0[0] = val;
            }
            if (botFix) {                        // row 511 := row 510
                *(u64*)&B[72][sc] = keep;
                if (colC) *(u64*)&f0[GN] = keep;
            }
        }
        __syncthreads();
    }
}

extern "C" void kernel_launch(void* const* d_in, const int* in_sizes, int n_in,
                              void* d_out, int out_size)
{
    (void)in_sizes; (void)n_in; (void)out_size;
    const float* u0 = (const float*)d_in[0];
    const float* k1 = (const float*)d_in[1];
    const float* k2 = (const float*)d_in[2];
    const float* a1 = (const float*)d_in[3];
    const float* a2 = (const float*)d_in[4];
    float* out = (float*)d_out;

    dim3 grid(GN / TBC, GN / TBR);   // 16 x 8 = 128 CTAs
    dim3 block(NT);

    int done = 0;
    const float* src = u0;
    while (done < TOTAL_STEPS) {
        int steps = TOTAL_STEPS - done;
        if (steps >= TD) {
            adr_chunk<TD><<<grid, block>>>(src, out + (size_t)done * GN * GN,
                                           k1, k2, a1, a2);
            steps = TD;
        } else {
            adr_chunk<TD - 1><<<grid, block>>>(src, out + (size_t)done * GN * GN,
                                               k1, k2, a1, a2);  // final 7-step chunk
        }
        src = out + (size_t)(done + steps - 1) * GN * GN;
        done += steps;
    }
}

// round 6
// speedup vs baseline: 1.9297x; 1.0483x over previous
#include <cuda_runtime.h>

#define GN 512
#define TBR 64          // tile rows
#define TBC 32          // tile cols
#define TD 8            // max temporal depth per launch
#define ROWS_P 82       // padded smem rows (region 80 + ring)
#define COLS_P 56       // float stride: 2-row offset 112 = 16 mod 32 -> conflict-free LDS.128
#define NGRP 12         // 4-column groups per region (48 cols)
#define NT 480          // 12 groups x 40 two-row strips
#define TOTAL_STEPS 199

typedef unsigned long long u64;

__device__ __forceinline__ u64 PK(float a, float b) {
    u64 r; asm("mov.b64 %0,{%1,%2};" : "=l"(r) : "f"(a), "f"(b)); return r;
}
__device__ __forceinline__ void UNPK(u64 v, float& a, float& b) {
    asm("mov.b64 {%0,%1},%2;" : "=f"(a), "=f"(b) : "l"(v));
}
__device__ __forceinline__ u64 ADD2(u64 a, u64 b) {
    u64 d; asm("add.rn.f32x2 %0,%1,%2;" : "=l"(d) : "l"(a), "l"(b)); return d;
}
__device__ __forceinline__ u64 MUL2(u64 a, u64 b) {
    u64 d; asm("mul.rn.f32x2 %0,%1,%2;" : "=l"(d) : "l"(a), "l"(b)); return d;
}
__device__ __forceinline__ u64 FMA2(u64 a, u64 b, u64 c) {
    u64 d; asm("fma.rn.f32x2 %0,%1,%2,%3;" : "=l"(d) : "l"(a), "l"(b), "l"(c)); return d;
}

// new(i,j) = V(clamp(i,1,510), clamp(j,1,510)); state extended by clamp(.,0,511).
// 64x32 tiles -> 128 CTAs (one per SM). Full 80x48 region recomputed per step in a
// garbage-ringed smem buffer; contamination creeps 1 cell/step so the central 64x32
// stays exact for up to 8 steps. Thread = 4-column group x 2-row strip; vertical
// neighbors via conflict-free LDS.128, inner horizontal neighbors from the same
// float4, outer edges via 2 scalar LDS. All math packed f32x2. Specials are
// branchless blends; group alignment (4 | 256) keeps material per-group uniform.
template <int NSTEPS>
__global__ __launch_bounds__(NT) void adr_chunk(
    const float* __restrict__ in_state,
    float* __restrict__ frames,
    const float* __restrict__ k1p, const float* __restrict__ k2p,
    const float* __restrict__ a1p, const float* __restrict__ a2p)
{
    __shared__ __align__(16) float buf[2][ROWS_P][COLS_P];

    const float k1 = __ldg(k1p), k2 = __ldg(k2p);
    const float a1 = __ldg(a1p), a2 = __ldg(a2p);
    const float inv_k12 = 1.0f / (k1 + k2);
    const float inv_dx2 = 511.0f * 511.0f;
    const float inv_2dx = 255.5f;
    const float DTC = 1e-7f;

    const int by = blockIdx.y, bx = blockIdx.x;
    const int r0 = by * TBR - TD;
    const int c0 = bx * TBC - TD;
    const int g  = (int)threadIdx.x % NGRP;    // 4-col group 0..11
    const int ty = (int)threadIdx.x / NGRP;    // strip 0..39 (2 rows)
    const int rbase = ty * 2;                  // first computed region row
    const int gj0 = c0 + 4 * g;                // global col of group lo
    const int sc  = 4 * g + 4;                 // smem col of group lo (16B aligned)

    const float kap = (gj0 < 256) ? k1 : k2;   // never straddles (4 | 256)
    const float al  = (gj0 < 256) ? a1 : a2;

    const float A1 = DTC * al * inv_dx2;
    const u64 cA1   = PK(A1, A1);
    const u64 cM4A1 = PK(-4.0f * A1, -4.0f * A1);
    const u64 cM1   = PK(-1.0f, -1.0f);
    const u64 cONE  = PK(1.0f, 1.0f);
    const u64 cI2   = PK(inv_2dx, inv_2dx);
    const u64 cMI2  = PK(-inv_2dx, -inv_2dx);
    const u64 cB1   = PK(DTC * kap, DTC * kap);

    const bool colC = (g >= 2) && (g <= 9);            // central 32 cols
    const bool rowC = (ty >= 4) && (ty <= 35);         // central 64 rows
    const bool storeC = colC && rowC;
    const bool isI  = (gj0 == 252);                    // group holding col 255
    const bool isL  = (gj0 == 0);
    const bool isR  = (gj0 == 508);                    // group holding col 511
    const bool topFix = (by == 0) && (ty == 4);            // global rows 0,1
    const bool botFix = (by == GN / TBR - 1) && (ty == 35); // global rows 510,511

    // stencil for one column pair (packed)
    auto pointPair = [&](u64 Tm, u64 Tc, u64 Tp, u64 L, u64 R) -> u64 {
        u64 sum  = ADD2(ADD2(Tm, Tp), ADD2(L, R));
        u64 lapc = FMA2(Tc, cM4A1, MUL2(sum, cA1));   // DT*al*lap
        u64 dxv  = FMA2(Tm, cM1, Tp);                  // Tp - Tm
        u64 dyv  = FMA2(L,  cM1, R);                   // R - L
        u64 P    = FMA2(dxv, cMI2, ADD2(Tc, cM1));     // (c-1) - T_x
        u64 Q    = FMA2(dyv, cI2,  cONE);              // T_y + 1
        u64 S    = FMA2(MUL2(Tc, Tc), P, MUL2(Tc, Q)); // c^2*P + c*Q
        return ADD2(Tc, FMA2(S, cB1, lapc));
    };

    // one full row of the group (4 cols) with branchless specials
    auto rowcalc = [&](float4 Fm, float4 Fc, float4 Fp, float TlS, float TrS,
                       u64& v0, u64& v1) {
        u64 Tm0 = PK(Fm.x, Fm.y), Tc0 = PK(Fc.x, Fc.y), Tp0 = PK(Fp.x, Fp.y);
        u64 Tm1 = PK(Fm.z, Fm.w), Tc1 = PK(Fc.z, Fc.w), Tp1 = PK(Fp.z, Fp.w);
        u64 L0 = PK(TlS, Fc.x);
        u64 M  = PK(Fc.y, Fc.z);      // R of pair0 == L of pair1
        u64 R1 = PK(Fc.w, TrS);
        v0 = pointPair(Tm0, Tc0, Tp0, L0, M);
        v1 = pointPair(Tm1, Tc1, Tp1, M, R1);
        float a, b;
        UNPK(v1, a, b);
        float ifv = fmaf(k1, TrS, k2 * Fc.z) * inv_k12;  // interface col 255
        b = isI ? ifv : b;
        b = isR ? a : b;                                  // col 511 := 510
        v1 = PK(a, b);
        UNPK(v0, a, b);
        a = isL ? b : a;                                  // col 0 := 1
        v0 = PK(a, b);
    };

    auto F4 = [](u64 v0, u64 v1) -> float4 {
        float a, b, c, d; UNPK(v0, a, b); UNPK(v1, c, d);
        return make_float4(a, b, c, d);
    };

    // ---- load region (extended via clamp); pad ring stays garbage ----
    {
        const bool canVec = (gj0 >= 0) && (gj0 + 3 < GN);
        #pragma unroll
        for (int rr = 0; rr < 2; ++rr) {
            int gi = r0 + rbase + rr;
            int li = min(max(gi, 0), GN - 1);
            float4 v;
            if (canVec) {
                v = *(const float4*)&in_state[(size_t)li * GN + gj0];
            } else {
                int j0 = min(max(gj0 + 0, 0), GN - 1);
                int j1 = min(max(gj0 + 1, 0), GN - 1);
                int j2 = min(max(gj0 + 2, 0), GN - 1);
                int j3 = min(max(gj0 + 3, 0), GN - 1);
                v = make_float4(in_state[(size_t)li * GN + j0],
                                in_state[(size_t)li * GN + j1],
                                in_state[(size_t)li * GN + j2],
                                in_state[(size_t)li * GN + j3]);
            }
            *(float4*)&buf[0][rbase + rr + 1][sc] = v;
        }
    }
    __syncthreads();

    float* const fr0 = frames + (ptrdiff_t)(r0 + rbase) * GN + gj0;

    #pragma unroll
    for (int s = 0; s < NSTEPS; ++s) {
        const float (*A)[COLS_P] = buf[s & 1];
        float (*B)[COLS_P] = buf[(s & 1) ^ 1];
        float* f0 = fr0 + (size_t)s * (GN * GN);

        float4 F0 = *(const float4*)&A[rbase + 0][sc];
        float4 F1 = *(const float4*)&A[rbase + 1][sc];
        float4 F2 = *(const float4*)&A[rbase + 2][sc];
        float4 F3 = *(const float4*)&A[rbase + 3][sc];
        float TlA = A[rbase + 1][sc - 1], TrA = A[rbase + 1][sc + 4];
        float TlB = A[rbase + 2][sc - 1], TrB = A[rbase + 2][sc + 4];

        u64 a0, a1v, b0, b1v;
        rowcalc(F0, F1, F2, TlA, TrA, a0, a1v);   // region row rbase
        rowcalc(F1, F2, F3, TlB, TrB, b0, b1v);   // region row rbase+1

        float4 VA = F4(a0, a1v);
        float4 VB = F4(b0, b1v);
        *(float4*)&B[rbase + 1][sc] = VA;
        *(float4*)&B[rbase + 2][sc] = VB;
        if (storeC) {
            *(float4*)&f0[0]  = VA;
            *(float4*)&f0[GN] = VB;
        }
        if (topFix) {               // global row 0 := row 1 (same-thread overwrite)
            *(float4*)&B[9][sc] = VB;
            if (colC) *(float4*)&f0[0] = VB;
        }
        if (botFix) {               // global row 511 := row 510
            *(float4*)&B[72][sc] = VA;
            if (colC) *(float4*)&f0[GN] = VA;
        }
        __syncthreads();
    }
}

extern "C" void kernel_launch(void* const* d_in, const int* in_sizes, int n_in,
                              void* d_out, int out_size)
{
    (void)in_sizes; (void)n_in; (void)out_size;
    const float* u0 = (const float*)d_in[0];
    const float* k1 = (const float*)d_in[1];
    const float* k2 = (const float*)d_in[2];
    const float* a1 = (const float*)d_in[3];
    const float* a2 = (const float*)d_in[4];
    float* out = (float*)d_out;

    dim3 grid(GN / TBC, GN / TBR);   // 16 x 8 = 128 CTAs
    dim3 block(NT);

    int done = 0;
    const float* src = u0;
    while (done < TOTAL_STEPS) {
        int steps = TOTAL_STEPS - done;
        if (steps >= TD) {
            adr_chunk<TD><<<grid, block>>>(src, out + (size_t)done * GN * GN,
                                           k1, k2, a1, a2);
            steps = TD;
        } else {
            adr_chunk<TD - 1><<<grid, block>>>(src, out + (size_t)done * GN * GN,
                                               k1, k2, a1, a2);  // final 7-step chunk
        }
        src = out + (size_t)(done + steps - 1) * GN * GN;
        done += steps;
    }
}